// round 12
// baseline (speedup 1.0000x reference)
#include <cuda_runtime.h>
#include <cuda_bf16.h>

#define BB 64
#define VV 64
#define TT 256
#define FF 64
#define AP  68    // adj row pitch: 16B-aligned, LDS.128 conflict-free

// transposed X: Xt[t][b][w]  (4 MB scratch)
__device__ float g_xt[TT * BB * VV];

// ---------------------------------------------------------------------------
// k0: Xt[t][b][w] = X[b][w][t]. Block = (tc, b), 64x64 tile in smem.
// Reads coalesced along t, writes coalesced along w. 8 MB total traffic.
// ---------------------------------------------------------------------------
__global__ __launch_bounds__(256)
void k0_xt(const float* __restrict__ X, float* __restrict__ Xt)
{
    __shared__ float st[64][65];        // [t_local][w], pad: conflict-free both ways
    const int tc  = blockIdx.x;         // t chunk 0..3
    const int b   = blockIdx.y;         // 0..63
    const int tid = threadIdx.x;

    // read X[b][w][tc*64 + tl], lanes sweep tl -> coalesced
    #pragma unroll
    for (int k = 0; k < 16; ++k) {
        int i  = tid + k * 256;         // 0..4095
        int w  = i >> 6, tl = i & 63;
        st[tl][w] = X[(size_t)b * (VV * TT) + (size_t)w * TT + tc * 64 + tl];
    }
    __syncthreads();

    // write Xt[(tc*64+tl)][b][w] as float4, lanes sweep w4 -> coalesced
    float4* Ot = reinterpret_cast<float4*>(Xt);
    #pragma unroll
    for (int k = 0; k < 4; ++k) {
        int i  = tid + k * 256;         // 0..1023
        int tl = i >> 4, w4 = i & 15;
        float4 v = make_float4(st[tl][w4 * 4 + 0], st[tl][w4 * 4 + 1],
                               st[tl][w4 * 4 + 2], st[tl][w4 * 4 + 3]);
        Ot[(size_t)(tc * 64 + tl) * (BB * VV / 4) + b * (VV / 4) + w4] = v;
    }
}

// ---------------------------------------------------------------------------
// main: block = (hp, t): one timestep, 32 batches (A redundancy only 2x/t).
// NT=512: 16 warps, each owns rows bl=wid and wid+16 end-to-end.
//  stage adj (sigmoid) + xs (contiguous 8KB from Xt); ONE __syncthreads.
//  warp: dot r1, dot r2 (LDS.128 conflict-free) -> streams 2 x 16KB (__stcs).
// ---------------------------------------------------------------------------
__global__ __launch_bounds__(512, 4)
void gnn_fused(const float* __restrict__ Xt,
               const float* __restrict__ A,
               const float* __restrict__ W,
               float* __restrict__ out)
{
    __shared__ float adj[VV][AP];       // 17.4 KB
    __shared__ float xs[32][VV];        // 8 KB
    __shared__ float hs[32][VV];        // 8 KB

    const int hp  = blockIdx.x;         // 0..1 (fast dim: same-t pair adjacent)
    const int t   = blockIdx.y;         // 0..255
    const int tid = threadIdx.x;
    const int wid = tid >> 5;           // 0..15
    const int lid = tid & 31;
    const int b0  = hp * 32;

    // ---- adj = sigmoid(A_t) off-diag, 1 on diag; 2 float4/thread ----
    const float4* Ag = reinterpret_cast<const float4*>(A + (size_t)t * VV * VV);
    #pragma unroll
    for (int k = 0; k < 2; ++k) {
        int i  = tid + k * 512;         // f4 idx 0..1023, coalesced (L2-hot x2)
        int v  = i >> 4;
        int w4 = i & 15;
        float4 a = Ag[i];
        float4 s;
        s.x = 1.0f / (1.0f + __expf(-a.x));
        s.y = 1.0f / (1.0f + __expf(-a.y));
        s.z = 1.0f / (1.0f + __expf(-a.z));
        s.w = 1.0f / (1.0f + __expf(-a.w));
        int wbase = w4 * 4;
        if (v == wbase + 0) s.x = 1.0f;
        if (v == wbase + 1) s.y = 1.0f;
        if (v == wbase + 2) s.z = 1.0f;
        if (v == wbase + 3) s.w = 1.0f;
        *reinterpret_cast<float4*>(&adj[v][wbase]) = s;
    }

    // ---- stage xs: contiguous 8 KB slab Xt[t][b0..b0+31][:], 1 f4/thread ----
    {
        const float4* src = reinterpret_cast<const float4*>(
            Xt + (size_t)t * (BB * VV) + b0 * VV);
        int bl = tid >> 4, w4 = tid & 15;
        float4 v = src[tid];            // fully coalesced
        *reinterpret_cast<float4*>(&xs[bl][w4 * 4]) = v;
    }

    const float4 wv = reinterpret_cast<const float4*>(W)[lid & 15];

    __syncthreads();                    // ONLY block-wide barrier

    // ---- warp-private dots for rows r1=wid, r2=wid+16 (split: low live range) ----
    #pragma unroll
    for (int half = 0; half < 2; ++half) {
        const int r = wid + half * 16;
        float s0 = 0.f, s1 = 0.f;
        #pragma unroll
        for (int w4 = 0; w4 < 16; ++w4) {
            float4 p = *reinterpret_cast<const float4*>(&adj[lid     ][w4 * 4]);
            float4 q = *reinterpret_cast<const float4*>(&adj[lid + 32][w4 * 4]);
            float4 x = *reinterpret_cast<const float4*>(&xs[r][w4 * 4]);   // bcast
            s0 = fmaf(p.x, x.x, s0); s0 = fmaf(p.y, x.y, s0);
            s0 = fmaf(p.z, x.z, s0); s0 = fmaf(p.w, x.w, s0);
            s1 = fmaf(q.x, x.x, s1); s1 = fmaf(q.y, x.y, s1);
            s1 = fmaf(q.z, x.z, s1); s1 = fmaf(q.w, x.w, s1);
        }
        hs[r][lid]      = s0;
        hs[r][lid + 32] = s1;
    }
    __syncwarp();

    // ---- warp streams its two 16 KB rows; no block barrier ----
    #pragma unroll
    for (int half = 0; half < 2; ++half) {
        const int r = wid + half * 16;
        float4* o = reinterpret_cast<float4*>(
            out + ((size_t)(b0 + r) * TT + t) * (VV * FF));
        #pragma unroll 4
        for (int j = 0; j < (VV * FF / 4) / 32; ++j) {   // 32 iters
            int p = j * 32 + lid;
            float h = hs[r][p >> 4];
            float4 rr;
            rr.x = h * wv.x; rr.y = h * wv.y; rr.z = h * wv.z; rr.w = h * wv.w;
            rr.x = fmaxf(rr.x, 0.01f * rr.x);
            rr.y = fmaxf(rr.y, 0.01f * rr.y);
            rr.z = fmaxf(rr.z, 0.01f * rr.z);
            rr.w = fmaxf(rr.w, 0.01f * rr.w);
            __stcs(&o[p], rr);
        }
    }
}

extern "C" void kernel_launch(void* const* d_in, const int* in_sizes, int n_in,
                              void* d_out, int out_size) {
    const float* X = (const float*)d_in[0];   // [64, 64, 256]
    const float* A = (const float*)d_in[1];   // [256, 64, 64]
    const float* W = (const float*)d_in[2];   // [64, 1]
    float* out = (float*)d_out;               // [64, 256, 4096]
    (void)in_sizes; (void)n_in; (void)out_size;

    float* xt;
    cudaGetSymbolAddress((void**)&xt, g_xt);

    dim3 g0(TT / 64, BB);                     // (4, 64)
    k0_xt<<<g0, 256>>>(X, xt);

    dim3 g1(2, TT);                           // (2, 256) = 512 blocks of 512 thr
    gnn_fused<<<g1, 512>>>(xt, A, W, out);
}

// round 13
// speedup vs baseline: 2.1700x; 2.1700x over previous
#include <cuda_runtime.h>
#include <cuda_bf16.h>

#define BB 64
#define VV 64
#define TT 256
#define FF 64
#define NT  256
#define BPB 8
#define AP  68    // adj row pitch: 16B-aligned, LDS.128 conflict-free (68 mod 32 = 4)

// transposed X: Xt[t][b][w]  (4 MB scratch) — proven exact in R12
__device__ float g_xt[TT * BB * VV];

// fast sigmoid: 1 MUFU (EX2) + bit-trick reciprocal + 2 Newton steps (~1e-6 rel)
__device__ __forceinline__ float fsig(float a) {
    float e = __expf(-a);
    float d = 1.0f + e;
    float y = __uint_as_float(0x7EF311C3u - __float_as_uint(d));
    y = y * (2.0f - d * y);
    y = y * (2.0f - d * y);
    return y;
}

// ---------------------------------------------------------------------------
// k0: Xt[t][b][w] = X[b][w][t]. Block = (tc, b), 64x64 smem tile; both sides
// coalesced. 8 MB total traffic (~1.3 us).
// ---------------------------------------------------------------------------
__global__ __launch_bounds__(256)
void k0_xt(const float* __restrict__ X, float* __restrict__ Xt)
{
    __shared__ float st[64][65];
    const int tc  = blockIdx.x;         // 0..3
    const int b   = blockIdx.y;         // 0..63
    const int tid = threadIdx.x;

    #pragma unroll
    for (int k = 0; k < 16; ++k) {
        int i  = tid + k * 256;
        int w  = i >> 6, tl = i & 63;
        st[tl][w] = X[(size_t)b * (VV * TT) + (size_t)w * TT + tc * 64 + tl];
    }
    __syncthreads();

    float4* Ot = reinterpret_cast<float4*>(Xt);
    #pragma unroll
    for (int k = 0; k < 4; ++k) {
        int i  = tid + k * 256;
        int tl = i >> 4, w4 = i & 15;
        float4 v = make_float4(st[tl][w4 * 4 + 0], st[tl][w4 * 4 + 1],
                               st[tl][w4 * 4 + 2], st[tl][w4 * 4 + 3]);
        Ot[(size_t)(tc * 64 + tl) * (BB * VV / 4) + b * (VV / 4) + w4] = v;
    }
}

// ---------------------------------------------------------------------------
// main: R10 skeleton. Block = (bc, t), bc fast => same-t blocks co-resident,
// A[t] L2-hot. Warp wid owns batch row b0+wid end-to-end; ONE block barrier.
// ---------------------------------------------------------------------------
__global__ __launch_bounds__(NT, 8)
void gnn_fused(const float* __restrict__ Xt,
               const float* __restrict__ A,
               const float* __restrict__ W,
               float* __restrict__ out)
{
    __shared__ float adj[VV][AP];       // 17.4 KB
    __shared__ float xs[BPB][VV];       // 2 KB
    __shared__ float hs[BPB][VV];       // 2 KB

    const int bc  = blockIdx.x;         // 0..7 (fast)
    const int t   = blockIdx.y;         // 0..255
    const int tid = threadIdx.x;
    const int wid = tid >> 5;           // 0..7 == batch row
    const int lid = tid & 31;
    const int b0  = bc * BPB;

    // ---- adj = fsig(A_t) off-diag, 1 on diag; 4 f4/thread, unroll 2 ----
    const float4* Ag = reinterpret_cast<const float4*>(A + (size_t)t * VV * VV);
    #pragma unroll 2
    for (int k = 0; k < 4; ++k) {
        int i  = tid + k * NT;
        int v  = i >> 4;
        int w4 = i & 15;
        float4 a = Ag[i];
        float4 s;
        s.x = fsig(a.x); s.y = fsig(a.y); s.z = fsig(a.z); s.w = fsig(a.w);
        int wbase = w4 * 4;
        if (v == wbase + 0) s.x = 1.0f;
        if (v == wbase + 1) s.y = 1.0f;
        if (v == wbase + 2) s.z = 1.0f;
        if (v == wbase + 3) s.w = 1.0f;
        *reinterpret_cast<float4*>(&adj[v][wbase]) = s;
    }

    // ---- stage xs: contiguous 2 KB slab Xt[t][b0..b0+7][:] (128 f4) ----
    if (tid < (BPB * VV) / 4) {
        const float4* src = reinterpret_cast<const float4*>(
            Xt + ((size_t)t * BB + b0) * VV);
        float4 v = src[tid];                         // fully coalesced
        int bl = tid >> 4, w4 = tid & 15;
        *reinterpret_cast<float4*>(&xs[bl][w4 * 4]) = v;
    }

    const float4 wv = reinterpret_cast<const float4*>(W)[lid & 15];

    __syncthreads();                    // ONLY block-wide barrier

    // ---- warp-private dot: lane owns v=lid and v+32 of row bl=wid ----
    {
        float s0 = 0.f, s1 = 0.f;
        #pragma unroll
        for (int w4 = 0; w4 < 16; ++w4) {
            float4 p = *reinterpret_cast<const float4*>(&adj[lid     ][w4 * 4]); // conflict-free
            float4 q = *reinterpret_cast<const float4*>(&adj[lid + 32][w4 * 4]); // conflict-free
            float4 x = *reinterpret_cast<const float4*>(&xs[wid][w4 * 4]);       // warp bcast
            s0 = fmaf(p.x, x.x, s0); s0 = fmaf(p.y, x.y, s0);
            s0 = fmaf(p.z, x.z, s0); s0 = fmaf(p.w, x.w, s0);
            s1 = fmaf(q.x, x.x, s1); s1 = fmaf(q.y, x.y, s1);
            s1 = fmaf(q.z, x.z, s1); s1 = fmaf(q.w, x.w, s1);
        }
        hs[wid][lid]      = s0;
        hs[wid][lid + 32] = s1;
    }
    __syncwarp();

    // ---- warp streams its own 16 KB row (coalesced f4, evict-first) ----
    float4* o = reinterpret_cast<float4*>(
        out + ((size_t)(b0 + wid) * TT + t) * (VV * FF));
    #pragma unroll 4
    for (int j = 0; j < (VV * FF / 4) / 32; ++j) {   // 32 iters
        int p = j * 32 + lid;
        float h = hs[wid][p >> 4];
        float4 r;
        r.x = h * wv.x; r.y = h * wv.y; r.z = h * wv.z; r.w = h * wv.w;
        r.x = fmaxf(r.x, 0.01f * r.x);
        r.y = fmaxf(r.y, 0.01f * r.y);
        r.z = fmaxf(r.z, 0.01f * r.z);
        r.w = fmaxf(r.w, 0.01f * r.w);
        __stcs(&o[p], r);
    }
}

extern "C" void kernel_launch(void* const* d_in, const int* in_sizes, int n_in,
                              void* d_out, int out_size) {
    const float* X = (const float*)d_in[0];   // [64, 64, 256]
    const float* A = (const float*)d_in[1];   // [256, 64, 64]
    const float* W = (const float*)d_in[2];   // [64, 1]
    float* out = (float*)d_out;               // [64, 256, 4096]
    (void)in_sizes; (void)n_in; (void)out_size;

    float* xt;
    cudaGetSymbolAddress((void**)&xt, g_xt);

    dim3 g0(TT / 64, BB);                     // (4, 64)
    k0_xt<<<g0, 256>>>(X, xt);

    dim3 g1(BB / BPB, TT);                    // (8, 256): same-t blocks adjacent
    gnn_fused<<<g1, NT>>>(xt, A, W, out);
}